// round 17
// baseline (speedup 1.0000x reference)
#include <cuda_runtime.h>
#include <cuda_fp16.h>
#include <cstdint>

// ===========================================================================
// DNN+LSTM fused, fp16 mma.sync.m16n8k16 (f32 acc). R14: PERSISTENT CTAs
// (grid = #SMs, 512 thr), software-pipelined across row-blocks: the tail
// phases of block j are interleaved with the mainloop tiles of block j+1,
// sharing the per-tile __syncthreads as phase barriers. Tail smem disjoint
// from mainloop smem (181 KB total).
//   Y[B,512] = x @ Wb.T (Wb=[fc1_w; W_ih(i,g,o)[:,:512]])
//   d1=relu(Y0+b); d2=relu(d1@fc2.T+b); d3=d2@fc3.T+b
//   i/g/o = Ygate + d3@Wih[:,512:].T + b; c=sig(i)tanh(g); h=sig(o)tanh(c)
//   out = h @ fc_w.T + fc_b    (f-gate, W_hh, attention dead)
// ===========================================================================

#define PH 72      // fp16 row pitch (words)
#define PF3 40     // fc3 row pitch (K=64)
#define PB2 196    // preact half2 pitch (words)
#define PA 20      // mainloop A pitch (words), k32

// Mainloop B: fp16 ni-paired fragment layout, 16 tiles x 32KB
__device__ __align__(1024) uint32_t g_WbF[131072];
// Tail weight images: [0]=fc2(64x72), [4608]=fc3(128x40), [9728]=Wi(128x72),
// [18944]=Wg, [28160]=Wo, [37376]=fcw  -> 46592 words
__device__ __align__(1024) uint32_t g_WtF[46592];

__device__ __forceinline__ uint32_t h2pack(float a, float b) {
    __half2 h = __floats2half2_rn(a, b);
    return *reinterpret_cast<uint32_t*>(&h);
}
__device__ __forceinline__ void mma16(float* c, uint32_t a0, uint32_t a1,
                                      uint32_t a2, uint32_t a3,
                                      uint32_t b0, uint32_t b1) {
    asm volatile(
        "mma.sync.aligned.m16n8k16.row.col.f32.f16.f16.f32 "
        "{%0,%1,%2,%3},{%4,%5,%6,%7},{%8,%9},{%0,%1,%2,%3};"
        : "+f"(c[0]), "+f"(c[1]), "+f"(c[2]), "+f"(c[3])
        : "r"(a0), "r"(a1), "r"(a2), "r"(a3), "r"(b0), "r"(b1));
}
__device__ __forceinline__ float fsigm(float x) {
    float t = -1.442695041f * x, e, r;
    asm("ex2.approx.f32 %0, %1;" : "=f"(e) : "f"(t));
    float d = 1.0f + e;
    asm("rcp.approx.f32 %0, %1;" : "=f"(r) : "f"(d));
    return r;
}
__device__ __forceinline__ float ftanhA(float x) {
    return fmaf(2.0f, fsigm(2.0f * x), -1.0f);
}
__device__ __forceinline__ uint32_t smem_u32(const void* p) {
    return (uint32_t)__cvta_generic_to_shared(p);
}
__device__ __forceinline__ int kword(int k) {
    int kk = k & 15;
    return (k >> 4) * 8 + ((kk & 7) >> 1) * 2 + ((kk >> 3) & 1);
}

// ---------------------------------------------------------------------------
__global__ void pack_kernel(const float* __restrict__ fc1_w,
                            const float* __restrict__ fc2_w,
                            const float* __restrict__ fc3_w,
                            const float* __restrict__ W_ih,
                            const float* __restrict__ fc_w) {
    int w = blockIdx.x * 256 + threadIdx.x;
    if (w >= 131072 + 46592) return;
    if (w < 131072) {
        int tile = w >> 13;
        int rem  = w & 8191;
        int step = rem >> 12;
        int p    = (rem >> 7) & 31;
        int lane = (rem >> 2) & 31;
        int q    = rem & 3;
        int n = (2 * p + (q >> 1)) * 8 + (lane >> 2);
        int k = tile * 32 + step * 16 + 2 * (lane & 3) + 8 * (q & 1);
        float v0, v1;
        if (n < 128) { v0 = fc1_w[n * 512 + k]; v1 = fc1_w[n * 512 + k + 1]; }
        else {
            int sr = (n < 256) ? n - 128 : n;
            v0 = W_ih[(size_t)sr * 640 + k]; v1 = W_ih[(size_t)sr * 640 + k + 1];
        }
        g_WbF[w] = h2pack(v0, v1);
        return;
    }
    int t = w - 131072;
    const float* src; int ww, kc;
    if (t < 4608)       { int n = t / 72;            ww = t % 72;            kc = 128; src = fc2_w + n * 128; }
    else if (t < 9728)  { int t2 = t - 4608;  int n = t2 / 40; ww = t2 % 40; kc = 64;  src = fc3_w + n * 64; }
    else if (t < 18944) { int t2 = t - 9728;  int n = t2 / 72; ww = t2 % 72; kc = 128; src = W_ih + (size_t)n * 640 + 512; }
    else if (t < 28160) { int t2 = t - 18944; int n = t2 / 72; ww = t2 % 72; kc = 128; src = W_ih + (size_t)(256 + n) * 640 + 512; }
    else if (t < 37376) { int t2 = t - 28160; int n = t2 / 72; ww = t2 % 72; kc = 128; src = W_ih + (size_t)(384 + n) * 640 + 512; }
    else                { int t2 = t - 37376; int n = t2 / 72; ww = t2 % 72; kc = 128; src = fc_w + n * 128; }
    uint32_t val = 0;
    if (ww < (kc >> 1)) {
        int j = ww & 7;
        int k = (ww >> 3) * 16 + (j & 1) * 8 + (j >> 1) * 2;
        val = h2pack(src[k], src[k + 1]);
    }
    g_WtF[t] = val;
}

// ---------------------------------------------------------------------------
// tail GEMM (fp16, permuted rows). 16 warps: twm = warp>>3, twn = warp&7
// ---------------------------------------------------------------------------
template <int KSTEPS, int NT, int PA_, int PW_>
__device__ __forceinline__ void tgemm_h(const uint32_t* __restrict__ sAa,
                                        const uint32_t* __restrict__ sW,
                                        float tac[2][NT][4],
                                        int twm, int twn, int g, int t4) {
#pragma unroll
    for (int s = 0; s < KSTEPS; s++) {
        uint2 alo[2], ahi[2];
#pragma unroll
        for (int mi = 0; mi < 2; mi++) {
            const uint32_t* ap = sAa + (twm * 32 + mi * 16 + g) * PA_ + s * 8 + t4 * 2;
            alo[mi] = *(const uint2*)ap;
            ahi[mi] = *(const uint2*)(ap + 8 * PA_);
        }
#pragma unroll
        for (int ni = 0; ni < NT; ni++) {
            int n = (twn * NT + ni) * 8 + g;
            uint2 b = *(const uint2*)(sW + n * PW_ + s * 8 + t4 * 2);
#pragma unroll
            for (int mi = 0; mi < 2; mi++)
                mma16(tac[mi][ni], alo[mi].x, ahi[mi].x, alo[mi].y, ahi[mi].y, b.x, b.y);
        }
    }
}

// ---------------------------------------------------------------------------
// smem (181248 B, all regions DISJOINT):
//  sA  @0      : 2 x 1280 w  (10240)
//  sB  @10240  : 2 x 8192 w  (65536)
//  B0  @75776  : 64 x 72 w   (18432)  fp16 activations (d1/d2/d3/h)
//  B2H @94208  : 64 x 196 w  (50176)  half2 gate preacts
//  Wbuf@144384 : 9216 w      (36864)  tail weight (cycled)
// ---------------------------------------------------------------------------
__global__ void __launch_bounds__(512, 1) fused_kernel(
    const float* __restrict__ x,
    const float* __restrict__ fc1_b, const float* __restrict__ fc2_b,
    const float* __restrict__ fc3_b, const float* __restrict__ b_ih,
    const float* __restrict__ b_hh,  const float* __restrict__ fc_b,
    float* __restrict__ out) {
    extern __shared__ char smem[];
    uint32_t* sAp  = (uint32_t*)smem;
    uint32_t* sBp  = (uint32_t*)(smem + 10240);
    uint32_t* B0   = (uint32_t*)(smem + 75776);
    uint32_t* B2H  = (uint32_t*)(smem + 94208);
    uint32_t* Wbuf = (uint32_t*)(smem + 144384);
    const uint32_t sbase   = smem_u32(smem);
    const uint32_t sB_base = sbase + 10240;
    const uint32_t Wb_base = sbase + 144384;

    const int tid  = threadIdx.x;
    const int lane = tid & 31;
    const int warp = tid >> 5;
    const int g    = lane >> 2;
    const int t4   = lane & 3;
    const int wr   = warp >> 3;     // 0..1  (32-row group)
    const int wc   = warp & 7;      // 0..7  (64-col group)

    const int r_ = tid >> 3;        // 0..63
    const int c4 = (tid & 7) << 2;  // 0..28

    float acc[2][8][4];
#pragma unroll
    for (int mi = 0; mi < 2; mi++)
#pragma unroll
        for (int ni = 0; ni < 8; ni++)
#pragma unroll
            for (int e = 0; e < 4; e++) acc[mi][ni][e] = 0.0f;

    // tail pipeline state (live across tile intervals)
    float    tac1[2][1][4];
    float    tac2[2][2][4];
    uint32_t si2[2][2][2];
    float    ccf[2][2][4];
    uint32_t hh2[2][2][2];

    float4 av;

#define LDA_P(XP, T) do { av = *(const float4*)((XP) + (size_t)r_ * 512 + (T) * 32 + c4); } while (0)
#define STA_P(S) do { \
    uint32_t* d_ = sAp + (S) * 1280 + r_ * PA; \
    d_[kword(c4)]     = h2pack(av.x, av.y); \
    d_[kword(c4 + 2)] = h2pack(av.z, av.w); \
} while (0)
#define CPB_P(T, S) do { \
    const char* s_ = (const char*)g_WbF + (size_t)(T) * 32768 + tid * 16; \
    uint32_t d_ = sB_base + (S) * 32768 + tid * 16; \
    _Pragma("unroll") \
    for (int i_ = 0; i_ < 4; i_++) \
        asm volatile("cp.async.cg.shared.global [%0], [%1], 16;" \
                     :: "r"(d_ + i_ * 8192), "l"(s_ + i_ * 8192)); \
    asm volatile("cp.async.commit_group;" ::: "memory"); \
} while (0)
#define FILLW(off, bytes) do { \
    const char* s_ = (const char*)g_WtF + (off); \
    for (int o_ = tid * 16; o_ < (bytes); o_ += 8192) \
        asm volatile("cp.async.cg.shared.global [%0], [%1], 16;" \
                     :: "r"(Wb_base + o_), "l"(s_ + o_)); \
    asm volatile("cp.async.commit_group;" ::: "memory"); \
} while (0)
#define CPWAIT0() asm volatile("cp.async.wait_group 0;" ::: "memory")

#define MMA_TILE(cur) do { \
    _Pragma("unroll") \
    for (int s_ = 0; s_ < 2; s_++) { \
        uint2 alo[2], ahi[2]; \
        _Pragma("unroll") \
        for (int mi = 0; mi < 2; mi++) { \
            const uint32_t* ap = sAp + (cur) * 1280 + (wr * 32 + mi * 16 + g) * PA + s_ * 8 + t4 * 2; \
            alo[mi] = *(const uint2*)ap; \
            ahi[mi] = *(const uint2*)(ap + 8 * PA); \
        } \
        _Pragma("unroll") \
        for (int pi = 0; pi < 4; pi++) { \
            uint4 bq = *(const uint4*)(sBp + (cur) * 8192 + ((s_ * 32 + wc * 4 + pi) * 32 + lane) * 4); \
            _Pragma("unroll") \
            for (int mi = 0; mi < 2; mi++) { \
                mma16(acc[mi][2 * pi],     alo[mi].x, ahi[mi].x, alo[mi].y, ahi[mi].y, bq.x, bq.y); \
                mma16(acc[mi][2 * pi + 1], alo[mi].x, ahi[mi].x, alo[mi].y, ahi[mi].y, bq.z, bq.w); \
            } \
        } \
    } \
} while (0)

// ------ tail phases (operate on prev block's staged smem data) ------
#define PH_G1() do { \
    _Pragma("unroll") for (int mi = 0; mi < 2; mi++) \
        _Pragma("unroll") for (int e = 0; e < 4; e++) tac1[mi][0][e] = 0.f; \
    tgemm_h<8, 1, PH, PH>(B0, Wbuf, tac1, wr, wc, g, t4); \
} while (0)
#define PH_ST_D2() do { \
    int c = wc * 8 + t4 * 2; int w0 = kword(c); \
    _Pragma("unroll") for (int mi = 0; mi < 2; mi++) { \
        int r = wr * 32 + mi * 16 + g; \
        B0[r * PH + w0] = h2pack(fmaxf(tac1[mi][0][0] + fc2_b[c], 0.f), \
                                 fmaxf(tac1[mi][0][1] + fc2_b[c + 1], 0.f)); \
        B0[(r + 8) * PH + w0] = h2pack(fmaxf(tac1[mi][0][2] + fc2_b[c], 0.f), \
                                       fmaxf(tac1[mi][0][3] + fc2_b[c + 1], 0.f)); \
    } \
} while (0)
#define PH_G2() do { \
    _Pragma("unroll") for (int mi = 0; mi < 2; mi++) \
        _Pragma("unroll") for (int ni = 0; ni < 2; ni++) \
            _Pragma("unroll") for (int e = 0; e < 4; e++) tac2[mi][ni][e] = 0.f; \
    tgemm_h<4, 2, PH, PF3>(B0, Wbuf, tac2, wr, wc, g, t4); \
} while (0)
#define PH_ST_D3() do { \
    _Pragma("unroll") for (int mi = 0; mi < 2; mi++) \
        _Pragma("unroll") for (int ni = 0; ni < 2; ni++) { \
            int r = wr * 32 + mi * 16 + g; \
            int c = (wc * 2 + ni) * 8 + t4 * 2; int w0 = kword(c); \
            B0[r * PH + w0] = h2pack(tac2[mi][ni][0] + fc3_b[c], \
                                     tac2[mi][ni][1] + fc3_b[c + 1]); \
            B0[(r + 8) * PH + w0] = h2pack(tac2[mi][ni][2] + fc3_b[c], \
                                           tac2[mi][ni][3] + fc3_b[c + 1]); \
        } \
} while (0)
#define PH_GI() do { \
    float tg[2][2][4]; \
    _Pragma("unroll") for (int mi = 0; mi < 2; mi++) \
        _Pragma("unroll") for (int ni = 0; ni < 2; ni++) \
            _Pragma("unroll") for (int e = 0; e < 4; e++) tg[mi][ni][e] = 0.f; \
    tgemm_h<8, 2, PH, PH>(B0, Wbuf, tg, wr, wc, g, t4); \
    _Pragma("unroll") for (int mi = 0; mi < 2; mi++) \
        _Pragma("unroll") for (int ni = 0; ni < 2; ni++) \
            _Pragma("unroll") for (int eh = 0; eh < 2; eh++) { \
                int r = wr * 32 + mi * 16 + g + eh * 8; \
                float2 pv = __half22float2(*(const __half2*)&B2H[r * PB2 + (wc * 2 + ni) * 4 + t4]); \
                si2[mi][ni][eh] = h2pack(fsigm(tg[mi][ni][eh * 2] + pv.x), \
                                         fsigm(tg[mi][ni][eh * 2 + 1] + pv.y)); \
            } \
} while (0)
#define PH_GG() do { \
    float tg[2][2][4]; \
    _Pragma("unroll") for (int mi = 0; mi < 2; mi++) \
        _Pragma("unroll") for (int ni = 0; ni < 2; ni++) \
            _Pragma("unroll") for (int e = 0; e < 4; e++) tg[mi][ni][e] = 0.f; \
    tgemm_h<8, 2, PH, PH>(B0, Wbuf, tg, wr, wc, g, t4); \
    _Pragma("unroll") for (int mi = 0; mi < 2; mi++) \
        _Pragma("unroll") for (int ni = 0; ni < 2; ni++) \
            _Pragma("unroll") for (int eh = 0; eh < 2; eh++) { \
                int r = wr * 32 + mi * 16 + g + eh * 8; \
                float2 pv = __half22float2(*(const __half2*)&B2H[r * PB2 + 64 + (wc * 2 + ni) * 4 + t4]); \
                float2 sv = __half22float2(*(const __half2*)&si2[mi][ni][eh]); \
                ccf[mi][ni][eh * 2]     = sv.x * ftanhA(tg[mi][ni][eh * 2] + pv.x); \
                ccf[mi][ni][eh * 2 + 1] = sv.y * ftanhA(tg[mi][ni][eh * 2 + 1] + pv.y); \
            } \
} while (0)
#define PH_GO() do { \
    float tg[2][2][4]; \
    _Pragma("unroll") for (int mi = 0; mi < 2; mi++) \
        _Pragma("unroll") for (int ni = 0; ni < 2; ni++) \
            _Pragma("unroll") for (int e = 0; e < 4; e++) tg[mi][ni][e] = 0.f; \
    tgemm_h<8, 2, PH, PH>(B0, Wbuf, tg, wr, wc, g, t4); \
    _Pragma("unroll") for (int mi = 0; mi < 2; mi++) \
        _Pragma("unroll") for (int ni = 0; ni < 2; ni++) \
            _Pragma("unroll") for (int eh = 0; eh < 2; eh++) { \
                int r = wr * 32 + mi * 16 + g + eh * 8; \
                float2 pv = __half22float2(*(const __half2*)&B2H[r * PB2 + 128 + (wc * 2 + ni) * 4 + t4]); \
                hh2[mi][ni][eh] = h2pack(fsigm(tg[mi][ni][eh * 2] + pv.x) * ftanhA(ccf[mi][ni][eh * 2]), \
                                         fsigm(tg[mi][ni][eh * 2 + 1] + pv.y) * ftanhA(ccf[mi][ni][eh * 2 + 1])); \
            } \
} while (0)
#define PH_ST_H() do { \
    _Pragma("unroll") for (int mi = 0; mi < 2; mi++) \
        _Pragma("unroll") for (int ni = 0; ni < 2; ni++) { \
            int c = (wc * 2 + ni) * 8 + t4 * 2; int w0 = kword(c); \
            _Pragma("unroll") for (int eh = 0; eh < 2; eh++) { \
                int r = wr * 32 + mi * 16 + g + eh * 8; \
                B0[r * PH + w0] = hh2[mi][ni][eh]; \
            } \
        } \
} while (0)
#define PH_G4(PRB) do { \
    _Pragma("unroll") for (int mi = 0; mi < 2; mi++) \
        _Pragma("unroll") for (int ni = 0; ni < 2; ni++) \
            _Pragma("unroll") for (int e = 0; e < 4; e++) tac2[mi][ni][e] = 0.f; \
    tgemm_h<8, 2, PH, PH>(B0, Wbuf, tac2, wr, wc, g, t4); \
    _Pragma("unroll") for (int mi = 0; mi < 2; mi++) \
        _Pragma("unroll") for (int ni = 0; ni < 2; ni++) { \
            int r = wr * 32 + mi * 16 + g; \
            int c = (wc * 2 + ni) * 8 + t4 * 2; \
            *(float2*)(out + ((PRB) + r) * 128 + c) = \
                make_float2(tac2[mi][ni][0] + fc_b[c], tac2[mi][ni][1] + fc_b[c + 1]); \
            *(float2*)(out + ((PRB) + r + 8) * 128 + c) = \
                make_float2(tac2[mi][ni][2] + fc_b[c], tac2[mi][ni][3] + fc_b[c + 1]); \
        } \
} while (0)
#define S0_DUMP() do { \
    if (wc < 2) { \
        _Pragma("unroll") for (int mi = 0; mi < 2; mi++) \
            _Pragma("unroll") for (int ni = 0; ni < 8; ni++) { \
                int r = wr * 32 + mi * 16 + g; \
                int cg = wc * 64 + ni * 8 + t4 * 2; int w0 = kword(cg); \
                B0[r * PH + w0] = h2pack(fmaxf(acc[mi][ni][0] + fc1_b[cg], 0.f), \
                                         fmaxf(acc[mi][ni][1] + fc1_b[cg + 1], 0.f)); \
                B0[(r + 8) * PH + w0] = h2pack(fmaxf(acc[mi][ni][2] + fc1_b[cg], 0.f), \
                                               fmaxf(acc[mi][ni][3] + fc1_b[cg + 1], 0.f)); \
            } \
    } else { \
        _Pragma("unroll") for (int mi = 0; mi < 2; mi++) \
            _Pragma("unroll") for (int ni = 0; ni < 8; ni++) \
                _Pragma("unroll") for (int eh = 0; eh < 2; eh++) { \
                    int r = wr * 32 + mi * 16 + g + eh * 8; \
                    int cg = wc * 64 + ni * 8 + t4 * 2; \
                    int bi = (cg < 256) ? cg - 128 : cg; \
                    B2H[r * PB2 + ((cg - 128) >> 1)] = \
                        h2pack(acc[mi][ni][eh * 2]     + b_ih[bi]     + b_hh[bi], \
                               acc[mi][ni][eh * 2 + 1] + b_ih[bi + 1] + b_hh[bi + 1]); \
                } \
    } \
} while (0)

    // ---- prologue: fc2 -> Wbuf; tile 0 of first block ----
    size_t b = blockIdx.x;
    const int stride = gridDim.x;
    bool hp = false;
    size_t prb = 0;

    FILLW(0, 18432);   // fc2
    LDA_P(x + b * 64 * 512, 0);
    CPB_P(0, 0);
    STA_P(0);
    CPWAIT0();
    __syncthreads();

#pragma unroll 1
    for (;;) {
        const float* xg = x + b * 64 * 512;
#pragma unroll
        for (int t = 0; t < 16; t++) {
            const int cur = t & 1, nxt = cur ^ 1;
            if (t < 15) {
                LDA_P(xg, t + 1);
                CPB_P(t + 1, nxt);
            } else {
                size_t nb = b + stride;
                if (nb < 2048) { LDA_P(x + nb * 64 * 512, 0); CPB_P(0, nxt); }
            }
            MMA_TILE(cur);
            if (t < 15) { STA_P(nxt); }
            else { size_t nb = b + stride; if (nb < 2048) STA_P(nxt); }
            if (hp) {
                if (t == 0)  { FILLW(0, 18432); }                 // fc2 (next cycle)
                if (t == 1)  { PH_G1(); }
                if (t == 2)  { PH_ST_D2(); FILLW(18432, 20480); } // fc3
                if (t == 4)  { PH_G2(); }
                if (t == 5)  { PH_ST_D3(); FILLW(38912, 36864); } // Wi
                if (t == 7)  { PH_GI(); }
                if (t == 8)  { FILLW(75776, 36864); }             // Wg
                if (t == 10) { PH_GG(); }
                if (t == 11) { FILLW(112640, 36864); }            // Wo
                if (t == 13) { PH_GO(); }
                if (t == 14) { PH_ST_H(); FILLW(149504, 36864); } // fcw
                if (t == 15) { PH_G4(prb); }
            }
            CPWAIT0();
            __syncthreads();
        }
        // dump this block's Y -> tail staging; reset acc
        S0_DUMP();
        __syncthreads();
#pragma unroll
        for (int mi = 0; mi < 2; mi++)
#pragma unroll
            for (int ni = 0; ni < 8; ni++)
#pragma unroll
                for (int e = 0; e < 4; e++) acc[mi][ni][e] = 0.0f;
        hp = true;
        prb = b * 64;
        b += stride;
        if (b >= 2048) break;
    }

    // ---- peeled tail for the last block (Wbuf currently = fcw) ----
    FILLW(0, 18432); CPWAIT0(); __syncthreads();
    PH_G1(); __syncthreads();
    PH_ST_D2(); FILLW(18432, 20480); CPWAIT0(); __syncthreads();
    PH_G2(); __syncthreads();
    PH_ST_D3(); FILLW(38912, 36864); CPWAIT0(); __syncthreads();
    PH_GI(); __syncthreads();
    FILLW(75776, 36864); CPWAIT0(); __syncthreads();
    PH_GG(); __syncthreads();
    FILLW(112640, 36864); CPWAIT0(); __syncthreads();
    PH_GO(); __syncthreads();
    PH_ST_H(); FILLW(149504, 36864); CPWAIT0(); __syncthreads();
    PH_G4(prb);
}

// ---------------------------------------------------------------------------
extern "C" void kernel_launch(void* const* d_in, const int* in_sizes, int n_in,
                              void* d_out, int out_size) {
    const float* x     = (const float*)d_in[0];
    const float* fc1_w = (const float*)d_in[1];
    const float* fc1_b = (const float*)d_in[2];
    const float* fc2_w = (const float*)d_in[3];
    const float* fc2_b = (const float*)d_in[4];
    const float* fc3_w = (const float*)d_in[5];
    const float* fc3_b = (const float*)d_in[6];
    const float* W_ih  = (const float*)d_in[7];
    // d_in[8] = W_hh (dead: h_prev == 0)
    const float* b_ih  = (const float*)d_in[9];
    const float* b_hh  = (const float*)d_in[10];
    // d_in[11..12] = attn_w, attn_b (dead: softmax over length-1 seq == 1)
    const float* fc_w  = (const float*)d_in[13];
    const float* fc_b  = (const float*)d_in[14];
    float* out = (float*)d_out;

    const int smem = 181248;
    cudaFuncSetAttribute(fused_kernel, cudaFuncAttributeMaxDynamicSharedMemorySize, smem);

    int nsm = 148;
    cudaDeviceGetAttribute(&nsm, cudaDevAttrMultiProcessorCount, 0);
    if (nsm < 1 || nsm > 2048) nsm = 148;

    pack_kernel<<<694, 256>>>(fc1_w, fc2_w, fc3_w, W_ih, fc_w);
    fused_kernel<<<nsm, 512, smem>>>(x, fc1_b, fc2_b, fc3_b,
                                     b_ih, b_hh, fc_b, out);
}